// round 16
// baseline (speedup 1.0000x reference)
#include <cuda_runtime.h>
#include <cuda_bf16.h>

// Embedding gather: out[n, :] = embeddings[inputs[n], :]
// N = 16384 rows, EMB = 128 floats = 512 B per row.
//
// R15 probe: converged R14 structure + Blackwell 256-bit global ld/st.
//   - lane 0 fetches all 4 row indices in ONE LDG.128 (int4), shfl broadcast
//   - each LDG.256 instruction: lanes 0-15 carry row A, lanes 16-31 row B
//     (32 B per lane) -> 2 load instructions cover 4 rows; line-level MLP
//     identical to the winning MLP=4 config, half the LSU issue slots
//   - 2 STG.256 instructions store the 4 rows, fully coalesced
// Grid: 512 blocks x 256 threads = 4096 warps x 4 rows. Single wave.

#define N_ROWS   16384
#define EMB_FLOATS 128               // floats per row (512 B)
#define THREADS  256
#define ROWS_PER_WARP 4
#define WARPS_TOTAL   (N_ROWS / ROWS_PER_WARP)        // 4096
#define NBLOCKS       (WARPS_TOTAL / (THREADS / 32))  // 512

__device__ __forceinline__ void ldg256(const float* p, float* r) {
    asm volatile("ld.global.nc.v8.f32 {%0,%1,%2,%3,%4,%5,%6,%7}, [%8];"
                 : "=f"(r[0]), "=f"(r[1]), "=f"(r[2]), "=f"(r[3]),
                   "=f"(r[4]), "=f"(r[5]), "=f"(r[6]), "=f"(r[7])
                 : "l"(p));
}

__device__ __forceinline__ void stg256(float* p, const float* r) {
    asm volatile("st.global.v8.f32 [%0], {%1,%2,%3,%4,%5,%6,%7,%8};"
                 :: "l"(p),
                    "f"(r[0]), "f"(r[1]), "f"(r[2]), "f"(r[3]),
                    "f"(r[4]), "f"(r[5]), "f"(r[6]), "f"(r[7])
                 : "memory");
}

__global__ __launch_bounds__(THREADS)
void onehot_embed_gather_v8(const int* __restrict__ idx,
                            const float* __restrict__ emb,   // [VOCAB, 128]
                            float* __restrict__ out)          // [N, 128]
{
    const int warp = (blockIdx.x * THREADS + threadIdx.x) >> 5;
    const int lane = threadIdx.x & 31;
    const int row0 = warp * ROWS_PER_WARP;

    // Lane 0: one LDG.128 carrying all 4 row indices for this warp.
    int4 packed = make_int4(0, 0, 0, 0);
    if (lane == 0)
        packed = __ldg((const int4*)(idx + row0));

    int e[ROWS_PER_WARP];
    e[0] = __shfl_sync(0xFFFFFFFFu, packed.x, 0);
    e[1] = __shfl_sync(0xFFFFFFFFu, packed.y, 0);
    e[2] = __shfl_sync(0xFFFFFFFFu, packed.z, 0);
    e[3] = __shfl_sync(0xFFFFFFFFu, packed.w, 0);

    const int sub  = lane & 15;      // 32B chunk within the row (16 x 32B = 512B)
    const int half = lane >> 4;      // 0 -> first row of pair, 1 -> second

    // Per-lane gather addresses: instruction i covers rows {2i, 2i+1}.
    const int e0 = half ? e[1] : e[0];
    const int e1 = half ? e[3] : e[2];

    // Two independent 256-bit gather loads in flight (4 rows of lines total).
    float v0[8], v1[8];
    ldg256(emb + (long long)e0 * EMB_FLOATS + sub * 8, v0);
    ldg256(emb + (long long)e1 * EMB_FLOATS + sub * 8, v1);

    // Two coalesced 256-bit stores (each covers 2 full rows = 1024B/warp).
    stg256(out + (long long)(row0 + half)     * EMB_FLOATS + sub * 8, v0);
    stg256(out + (long long)(row0 + 2 + half) * EMB_FLOATS + sub * 8, v1);
}

extern "C" void kernel_launch(void* const* d_in, const int* in_sizes, int n_in,
                              void* d_out, int out_size)
{
    const int*   idx = (const int*)  d_in[0];   // int32 [16384]
    const float* emb = (const float*)d_in[1];   // float32 [32000,128]
    float*       out = (float*)      d_out;     // float32 [16384,128]

    onehot_embed_gather_v8<<<NBLOCKS, THREADS>>>(idx, emb, out);
}